// round 3
// baseline (speedup 1.0000x reference)
#include <cuda_runtime.h>

// SWT level-1 (db2, norm=True) along channel axis with periodic wrap.
// x:   [B=8, C=64, H=128, W=128] f32
// out: [B=8, 2C=128, H=128, W=128] f32  (cA in channels [0,64), cD in [64,128))
//
// cA[c] = lo[0]*x[c+2] + lo[1]*x[c+1] + lo[2]*x[c] + lo[3]*x[c-1]   (mod 64)
// cD[c] = hi[0]*x[c+2] + hi[1]*x[c+1] + hi[2]*x[c] + hi[3]*x[c-1]
//
// Strategy: one thread per spatial float4; sliding 4-register window over the
// 64 channels so every input element is loaded exactly once and produces both
// bands. Pure streaming: 33.5MB read + 67MB write ~= HBM roofline.

#define HW4 4096  // (128*128)/4 float4 per channel plane

__global__ __launch_bounds__(128)
void swt_db2_kernel(const float4* __restrict__ x, float4* __restrict__ out) {
    const float INV_SQRT2 = 0.70710678118654752440f;
    // pywt db2 dec filters / sqrt(2)
    const float lo0 = -0.12940952255092145f * INV_SQRT2;  // * x[c+2]
    const float lo1 =  0.22414386804185735f * INV_SQRT2;  // * x[c+1]
    const float lo2 =  0.83651630373746900f * INV_SQRT2;  // * x[c]
    const float lo3 =  0.48296291314469025f * INV_SQRT2;  // * x[c-1]
    const float hi0 = -0.48296291314469025f * INV_SQRT2;
    const float hi1 =  0.83651630373746900f * INV_SQRT2;
    const float hi2 = -0.22414386804185735f * INV_SQRT2;
    const float hi3 = -0.12940952255092145f * INV_SQRT2;

    int t = blockIdx.x * blockDim.x + threadIdx.x;   // 0 .. 32767
    int b = t >> 12;                                  // / 4096
    int s = t & 4095;                                 // float4 index in HxW plane

    const float4* xin = x   + ((size_t)b << 18) + s;  // b * 64 * 4096
    float4*       oA  = out + ((size_t)b << 19) + s;  // b * 128 * 4096
    float4*       oD  = oA + (size_t)64 * HW4;

    // window: wa = x[c-1], wb = x[c], wc = x[c+1]; wd loaded per-iteration = x[c+2]
    float4 wa = xin[(size_t)63 * HW4];
    float4 wb = xin[0];
    float4 wc = xin[(size_t)1 * HW4];

#pragma unroll 8
    for (int c = 0; c < 64; ++c) {
        float4 wd = xin[(size_t)((c + 2) & 63) * HW4];

        float4 A, D;
        A.x = fmaf(lo0, wd.x, fmaf(lo1, wc.x, fmaf(lo2, wb.x, lo3 * wa.x)));
        A.y = fmaf(lo0, wd.y, fmaf(lo1, wc.y, fmaf(lo2, wb.y, lo3 * wa.y)));
        A.z = fmaf(lo0, wd.z, fmaf(lo1, wc.z, fmaf(lo2, wb.z, lo3 * wa.z)));
        A.w = fmaf(lo0, wd.w, fmaf(lo1, wc.w, fmaf(lo2, wb.w, lo3 * wa.w)));
        D.x = fmaf(hi0, wd.x, fmaf(hi1, wc.x, fmaf(hi2, wb.x, hi3 * wa.x)));
        D.y = fmaf(hi0, wd.y, fmaf(hi1, wc.y, fmaf(hi2, wb.y, hi3 * wa.y)));
        D.z = fmaf(hi0, wd.z, fmaf(hi1, wc.z, fmaf(hi2, wb.z, hi3 * wa.z)));
        D.w = fmaf(hi0, wd.w, fmaf(hi1, wc.w, fmaf(hi2, wb.w, hi3 * wa.w)));

        oA[(size_t)c * HW4] = A;
        oD[(size_t)c * HW4] = D;

        wa = wb; wb = wc; wc = wd;
    }
}

extern "C" void kernel_launch(void* const* d_in, const int* in_sizes, int n_in,
                              void* d_out, int out_size) {
    const float4* x = (const float4*)d_in[0];
    float4* out = (float4*)d_out;
    // 8 * 128 * 128 spatial positions / 4 (float4) = 32768 threads
    swt_db2_kernel<<<256, 128>>>(x, out);
}

// round 4
// speedup vs baseline: 1.3235x; 1.3235x over previous
#include <cuda_runtime.h>

// SWT level-1 (db2, norm=True) along channel axis with periodic wrap.
// x:   [B=8, C=64, H=128, W=128] f32
// out: [B=8, 2C=128, H=128, W=128] f32  (cA in [0,64), cD in [64,128))
//
// cA[c] = lo0*x[c+2] + lo1*x[c+1] + lo2*x[c] + lo3*x[c-1]   (mod 64)
// cD[c] = hi0*x[c+2] + hi1*x[c+1] + hi2*x[c] + hi3*x[c-1]
//
// R3 strategy: channel-chunked for occupancy. Each thread owns one spatial
// float4 and an 8-channel chunk: front-loads 11 halo'd input planes into
// registers (MLP=11), then computes/stores 16 output planes.
// 262144 threads total -> ~42+ warps/SM; traffic = 46MB read + 67MB write.

#define HW4 4096  // (128*128)/4 float4 per channel plane
#define CHUNK 8

__global__ __launch_bounds__(256)
void swt_db2_kernel(const float4* __restrict__ x, float4* __restrict__ out) {
    const float INV_SQRT2 = 0.70710678118654752440f;
    const float lo0 = -0.12940952255092145f * INV_SQRT2;  // * x[c+2]
    const float lo1 =  0.22414386804185735f * INV_SQRT2;  // * x[c+1]
    const float lo2 =  0.83651630373746900f * INV_SQRT2;  // * x[c]
    const float lo3 =  0.48296291314469025f * INV_SQRT2;  // * x[c-1]
    const float hi0 = -0.48296291314469025f * INV_SQRT2;
    const float hi1 =  0.83651630373746900f * INV_SQRT2;
    const float hi2 = -0.22414386804185735f * INV_SQRT2;
    const float hi3 = -0.12940952255092145f * INV_SQRT2;

    int t = blockIdx.x * blockDim.x + threadIdx.x;   // 0 .. 262143
    int s     = t & 4095;          // float4 index within HxW plane
    int chunk = (t >> 12) & 7;     // which 8-channel chunk
    int b     = t >> 15;           // batch
    int c0    = chunk << 3;        // first output channel of this chunk

    const float4* xin = x   + ((size_t)b << 18) + s;                       // b*64*4096
    float4*       oA  = out + ((size_t)b << 19) + (size_t)c0 * HW4 + s;    // b*128*4096
    float4*       oD  = oA + (size_t)64 * HW4;

    // Front-load planes c0-1 .. c0+9 (mod 64): 11 independent LDG.128
    float4 w[CHUNK + 3];
#pragma unroll
    for (int k = 0; k < CHUNK + 3; ++k) {
        int c = (c0 + k + 63) & 63;   // c0-1+k, wrapped
        w[k] = xin[(size_t)c * HW4];
    }

#pragma unroll
    for (int i = 0; i < CHUNK; ++i) {
        // output channel c0+i uses x[c-1]=w[i], x[c]=w[i+1], x[c+1]=w[i+2], x[c+2]=w[i+3]
        float4 wa = w[i], wb = w[i + 1], wc = w[i + 2], wd = w[i + 3];
        float4 A, D;
        A.x = fmaf(lo0, wd.x, fmaf(lo1, wc.x, fmaf(lo2, wb.x, lo3 * wa.x)));
        A.y = fmaf(lo0, wd.y, fmaf(lo1, wc.y, fmaf(lo2, wb.y, lo3 * wa.y)));
        A.z = fmaf(lo0, wd.z, fmaf(lo1, wc.z, fmaf(lo2, wb.z, lo3 * wa.z)));
        A.w = fmaf(lo0, wd.w, fmaf(lo1, wc.w, fmaf(lo2, wb.w, lo3 * wa.w)));
        D.x = fmaf(hi0, wd.x, fmaf(hi1, wc.x, fmaf(hi2, wb.x, hi3 * wa.x)));
        D.y = fmaf(hi0, wd.y, fmaf(hi1, wc.y, fmaf(hi2, wb.y, hi3 * wa.y)));
        D.z = fmaf(hi0, wd.z, fmaf(hi1, wc.z, fmaf(hi2, wb.z, hi3 * wa.z)));
        D.w = fmaf(hi0, wd.w, fmaf(hi1, wc.w, fmaf(hi2, wb.w, hi3 * wa.w)));

        oA[(size_t)i * HW4] = A;
        oD[(size_t)i * HW4] = D;
    }
}

extern "C" void kernel_launch(void* const* d_in, const int* in_sizes, int n_in,
                              void* d_out, int out_size) {
    const float4* x = (const float4*)d_in[0];
    float4* out = (float4*)d_out;
    // 8 batches * 8 chunks * 4096 spatial float4 = 262144 threads
    swt_db2_kernel<<<1024, 256>>>(x, out);
}

// round 7
// speedup vs baseline: 1.3636x; 1.0303x over previous
#include <cuda_runtime.h>

// SWT level-1 (db2, norm=True) along channel axis with periodic wrap.
// x:   [B=8, C=64, H=128, W=128] f32
// out: [B=8, 2C=128, H=128, W=128] f32  (cA in [0,64), cD in [64,128))
//
// cA[c] = lo0*x[c+2] + lo1*x[c+1] + lo2*x[c] + lo3*x[c-1]   (mod 64)
// cD[c] = hi0*x[c+2] + hi1*x[c+1] + hi2*x[c] + hi3*x[c-1]
//
// R4: software-pipelined sliding window (1 load/iter, MLP_p1~3) instead of 11
// front-batched loads -> avoids the B300 cross-CTA L1tex-queue spread pathology
// and cuts live registers. __launch_bounds__(256,7) caps regs at 36 so all
// 8192 warps fit in a SINGLE wave (56 warps/SM * 148 = 8288).

#define HW4 4096  // (128*128)/4 float4 per channel plane
#define CHUNK 8

__global__ __launch_bounds__(256, 7)
void swt_db2_kernel(const float4* __restrict__ x, float4* __restrict__ out) {
    const float INV_SQRT2 = 0.70710678118654752440f;
    const float lo0 = -0.12940952255092145f * INV_SQRT2;  // * x[c+2]
    const float lo1 =  0.22414386804185735f * INV_SQRT2;  // * x[c+1]
    const float lo2 =  0.83651630373746900f * INV_SQRT2;  // * x[c]
    const float lo3 =  0.48296291314469025f * INV_SQRT2;  // * x[c-1]
    const float hi0 = -0.48296291314469025f * INV_SQRT2;
    const float hi1 =  0.83651630373746900f * INV_SQRT2;
    const float hi2 = -0.22414386804185735f * INV_SQRT2;
    const float hi3 = -0.12940952255092145f * INV_SQRT2;

    int t = blockIdx.x * blockDim.x + threadIdx.x;   // 0 .. 262143
    int s     = t & 4095;          // float4 index within HxW plane
    int chunk = (t >> 12) & 7;     // which 8-channel chunk
    int b     = t >> 15;           // batch
    int c0    = chunk << 3;        // first output channel of this chunk

    const float4* xin = x   + ((size_t)b << 18) + s;                     // b*64*4096
    float4*       oA  = out + ((size_t)b << 19) + (size_t)c0 * HW4 + s;  // b*128*4096
    float4*       oD  = oA + (size_t)64 * HW4;

    // Pre-load window: x[c0-1], x[c0], x[c0+1]  (periodic wrap)
    float4 w0 = xin[(size_t)((c0 + 63) & 63) * HW4];
    float4 w1 = xin[(size_t)c0 * HW4];
    float4 w2 = xin[(size_t)(c0 + 1) * HW4];   // c0+1 <= 57, no wrap needed

#pragma unroll
    for (int i = 0; i < CHUNK; ++i) {
        float4 w3 = xin[(size_t)((c0 + i + 2) & 63) * HW4];

        float4 A, D;
        A.x = fmaf(lo0, w3.x, fmaf(lo1, w2.x, fmaf(lo2, w1.x, lo3 * w0.x)));
        A.y = fmaf(lo0, w3.y, fmaf(lo1, w2.y, fmaf(lo2, w1.y, lo3 * w0.y)));
        A.z = fmaf(lo0, w3.z, fmaf(lo1, w2.z, fmaf(lo2, w1.z, lo3 * w0.z)));
        A.w = fmaf(lo0, w3.w, fmaf(lo1, w2.w, fmaf(lo2, w1.w, lo3 * w0.w)));
        D.x = fmaf(hi0, w3.x, fmaf(hi1, w2.x, fmaf(hi2, w1.x, hi3 * w0.x)));
        D.y = fmaf(hi0, w3.y, fmaf(hi1, w2.y, fmaf(hi2, w1.y, hi3 * w0.y)));
        D.z = fmaf(hi0, w3.z, fmaf(hi1, w2.z, fmaf(hi2, w1.z, hi3 * w0.z)));
        D.w = fmaf(hi0, w3.w, fmaf(hi1, w2.w, fmaf(hi2, w1.w, hi3 * w0.w)));

        oA[(size_t)i * HW4] = A;
        oD[(size_t)i * HW4] = D;

        w0 = w1; w1 = w2; w2 = w3;
    }
}

extern "C" void kernel_launch(void* const* d_in, const int* in_sizes, int n_in,
                              void* d_out, int out_size) {
    const float4* x = (const float4*)d_in[0];
    float4* out = (float4*)d_out;
    // 8 batches * 8 chunks * 4096 spatial float4 = 262144 threads
    swt_db2_kernel<<<1024, 256>>>(x, out);
}

// round 8
// speedup vs baseline: 1.5551x; 1.1404x over previous
#include <cuda_runtime.h>

// SWT level-1 (db2, norm=True) along channel axis with periodic wrap.
// x:   [B=8, C=64, H=128, W=128] f32
// out: [B=8, 2C=128, H=128, W=128] f32  (cA in [0,64), cD in [64,128))
//
// cA[c] = lo0*x[c+2] + lo1*x[c+1] + lo2*x[c] + lo3*x[c-1]   (mod 64)
// cD[c] = hi0*x[c+2] + hi1*x[c+1] + hi2*x[c] + hi3*x[c-1]
//
// R7: steady-state is DRAM-drain bound (~100MB compulsory traffic/launch).
//  - __stcs (evict-first) output stores: output is write-once, keep it from
//    thrashing input planes out of L2 -> input halo re-reads stay L2 hits.
//  - prefetch-distance-2 sliding window (2 LDGs in flight, peeled tail so
//    exactly 11 loads/thread, no waste).
//  - launch_bounds(256,6): 40-reg budget so the deeper pipeline doesn't spill.

#define HW4 4096  // (128*128)/4 float4 per channel plane
#define CHUNK 8

__global__ __launch_bounds__(256, 6)
void swt_db2_kernel(const float4* __restrict__ x, float4* __restrict__ out) {
    const float INV_SQRT2 = 0.70710678118654752440f;
    const float lo0 = -0.12940952255092145f * INV_SQRT2;  // * x[c+2]
    const float lo1 =  0.22414386804185735f * INV_SQRT2;  // * x[c+1]
    const float lo2 =  0.83651630373746900f * INV_SQRT2;  // * x[c]
    const float lo3 =  0.48296291314469025f * INV_SQRT2;  // * x[c-1]
    const float hi0 = -0.48296291314469025f * INV_SQRT2;
    const float hi1 =  0.83651630373746900f * INV_SQRT2;
    const float hi2 = -0.22414386804185735f * INV_SQRT2;
    const float hi3 = -0.12940952255092145f * INV_SQRT2;

    int t = blockIdx.x * blockDim.x + threadIdx.x;   // 0 .. 262143
    int s     = t & 4095;          // float4 index within HxW plane
    int chunk = (t >> 12) & 7;     // which 8-channel chunk
    int b     = t >> 15;           // batch
    int c0    = chunk << 3;        // first output channel of this chunk

    const float4* xin = x   + ((size_t)b << 18) + s;                     // b*64*4096
    float4*       oA  = out + ((size_t)b << 19) + (size_t)c0 * HW4 + s;  // b*128*4096
    float4*       oD  = oA + (size_t)64 * HW4;

    // Prologue: window planes c0-1..c0+1 plus two prefetched (c0+2, c0+3).
    float4 w0 = xin[(size_t)((c0 + 63) & 63) * HW4];
    float4 w1 = xin[(size_t)c0 * HW4];
    float4 w2 = xin[(size_t)(c0 + 1) * HW4];   // c0+1 <= 57, no wrap
    float4 p  = xin[(size_t)(c0 + 2) * HW4];   // c0+2 <= 58, no wrap
    float4 q  = xin[(size_t)(c0 + 3) * HW4];   // c0+3 <= 59, no wrap

#pragma unroll
    for (int i = 0; i < CHUNK; ++i) {
        float4 w3 = p;
        p = q;
        if (i < CHUNK - 2)  // peel: exactly 11 loads total, none wasted
            q = xin[(size_t)((c0 + i + 4) & 63) * HW4];

        float4 A, D;
        A.x = fmaf(lo0, w3.x, fmaf(lo1, w2.x, fmaf(lo2, w1.x, lo3 * w0.x)));
        A.y = fmaf(lo0, w3.y, fmaf(lo1, w2.y, fmaf(lo2, w1.y, lo3 * w0.y)));
        A.z = fmaf(lo0, w3.z, fmaf(lo1, w2.z, fmaf(lo2, w1.z, lo3 * w0.z)));
        A.w = fmaf(lo0, w3.w, fmaf(lo1, w2.w, fmaf(lo2, w1.w, lo3 * w0.w)));
        D.x = fmaf(hi0, w3.x, fmaf(hi1, w2.x, fmaf(hi2, w1.x, hi3 * w0.x)));
        D.y = fmaf(hi0, w3.y, fmaf(hi1, w2.y, fmaf(hi2, w1.y, hi3 * w0.y)));
        D.z = fmaf(hi0, w3.z, fmaf(hi1, w2.z, fmaf(hi2, w1.z, hi3 * w0.z)));
        D.w = fmaf(hi0, w3.w, fmaf(hi1, w2.w, fmaf(hi2, w1.w, hi3 * w0.w)));

        // Streaming stores: output is write-once, evict-first keeps input in L2.
        __stcs(&oA[(size_t)i * HW4], A);
        __stcs(&oD[(size_t)i * HW4], D);

        w0 = w1; w1 = w2; w2 = w3;
    }
}

extern "C" void kernel_launch(void* const* d_in, const int* in_sizes, int n_in,
                              void* d_out, int out_size) {
    const float4* x = (const float4*)d_in[0];
    float4* out = (float4*)d_out;
    // 8 batches * 8 chunks * 4096 spatial float4 = 262144 threads
    swt_db2_kernel<<<1024, 256>>>(x, out);
}

// round 10
// speedup vs baseline: 1.5859x; 1.0198x over previous
#include <cuda_runtime.h>

// SWT level-1 (db2, norm=True) along channel axis with periodic wrap.
// x:   [B=8, C=64, H=128, W=128] f32
// out: [B=8, 2C=128, H=128, W=128] f32  (cA in [0,64), cD in [64,128))
//
// cA[c] = lo0*x[c+2] + lo1*x[c+1] + lo2*x[c] + lo3*x[c-1]   (mod 64)
// cD[c] = hi0*x[c+2] + hi1*x[c+1] + hi2*x[c] + hi3*x[c-1]
//
// R8: double the warp count for more memory-system concurrency.
// CHUNK=4 -> 524288 threads (16384 warps). 7 loads + 8 stores per thread.
// Halo re-reads (1.75x) hit L2 (42% busy, headroom); DRAM traffic unchanged.
// __stcs streaming stores keep the input resident in L2.

#define HW4 4096  // (128*128)/4 float4 per channel plane
#define CHUNK 4

__global__ __launch_bounds__(256, 6)
void swt_db2_kernel(const float4* __restrict__ x, float4* __restrict__ out) {
    const float INV_SQRT2 = 0.70710678118654752440f;
    const float lo0 = -0.12940952255092145f * INV_SQRT2;  // * x[c+2]
    const float lo1 =  0.22414386804185735f * INV_SQRT2;  // * x[c+1]
    const float lo2 =  0.83651630373746900f * INV_SQRT2;  // * x[c]
    const float lo3 =  0.48296291314469025f * INV_SQRT2;  // * x[c-1]
    const float hi0 = -0.48296291314469025f * INV_SQRT2;
    const float hi1 =  0.83651630373746900f * INV_SQRT2;
    const float hi2 = -0.22414386804185735f * INV_SQRT2;
    const float hi3 = -0.12940952255092145f * INV_SQRT2;

    int t = blockIdx.x * blockDim.x + threadIdx.x;   // 0 .. 524287
    int s     = t & 4095;          // float4 index within HxW plane
    int chunk = (t >> 12) & 15;    // which 4-channel chunk
    int b     = t >> 16;           // batch
    int c0    = chunk << 2;        // first output channel of this chunk

    const float4* xin = x   + ((size_t)b << 18) + s;                     // b*64*4096
    float4*       oA  = out + ((size_t)b << 19) + (size_t)c0 * HW4 + s;  // b*128*4096
    float4*       oD  = oA + (size_t)64 * HW4;

    // Front-load the 7 planes c0-1 .. c0+5 (mod 64): 7 independent LDG.128.
    float4 w[CHUNK + 3];
#pragma unroll
    for (int k = 0; k < CHUNK + 3; ++k) {
        int c = (c0 + k + 63) & 63;   // c0-1+k, wrapped
        w[k] = xin[(size_t)c * HW4];
    }

#pragma unroll
    for (int i = 0; i < CHUNK; ++i) {
        float4 wa = w[i], wb = w[i + 1], wc = w[i + 2], wd = w[i + 3];
        float4 A, D;
        A.x = fmaf(lo0, wd.x, fmaf(lo1, wc.x, fmaf(lo2, wb.x, lo3 * wa.x)));
        A.y = fmaf(lo0, wd.y, fmaf(lo1, wc.y, fmaf(lo2, wb.y, lo3 * wa.y)));
        A.z = fmaf(lo0, wd.z, fmaf(lo1, wc.z, fmaf(lo2, wb.z, lo3 * wa.z)));
        A.w = fmaf(lo0, wd.w, fmaf(lo1, wc.w, fmaf(lo2, wb.w, lo3 * wa.w)));
        D.x = fmaf(hi0, wd.x, fmaf(hi1, wc.x, fmaf(hi2, wb.x, hi3 * wa.x)));
        D.y = fmaf(hi0, wd.y, fmaf(hi1, wc.y, fmaf(hi2, wb.y, hi3 * wa.y)));
        D.z = fmaf(hi0, wd.z, fmaf(hi1, wc.z, fmaf(hi2, wb.z, hi3 * wa.z)));
        D.w = fmaf(hi0, wd.w, fmaf(hi1, wc.w, fmaf(hi2, wb.w, hi3 * wa.w)));

        __stcs(&oA[(size_t)i * HW4], A);
        __stcs(&oD[(size_t)i * HW4], D);
    }
}

extern "C" void kernel_launch(void* const* d_in, const int* in_sizes, int n_in,
                              void* d_out, int out_size) {
    const float4* x = (const float4*)d_in[0];
    float4* out = (float4*)d_out;
    // 8 batches * 16 chunks * 4096 spatial float4 = 524288 threads
    swt_db2_kernel<<<2048, 256>>>(x, out);
}